// round 11
// baseline (speedup 1.0000x reference)
#include <cuda_runtime.h>
#include <cuda_fp16.h>
#include <cstdint>

// BahdanauAttention: B=32, SK=8192, D=128  (compute_100-safe: mma.sync fp16 single-pass)
// Single persistent kernel:
//   logit[b,s] = Wf . tanh(K[b,s] @ W1h + t[b]) + bf
//   e = exp(logit) (unshifted); denom/acc accumulated per batch
//   grid-wide barrier (all 296 CTAs co-resident) -> in-kernel normalize
// Output layout: [attn (32*128) | attn_sm (32*8192)]

#define B_    32
#define SK_   8192
#define D_    128
#define NTILE 4096          // 64-row tiles (32 b * 128)
#define GRID2 296

// ---------------- scratch (zero-initialized at load; self-cleaned each run) ----------------
__device__ float    g_denom[B_];
__device__ float    g_acc[B_ * D_];
__device__ unsigned g_bar;     // grid barrier arrivals
__device__ unsigned g_tick;    // post-normalize cleanup election

// ---------------- helpers ----------------
__device__ __forceinline__ uint32_t smem_u32(const void* p) {
    uint32_t r;
    asm("{ .reg .u64 t; cvta.to.shared.u64 t, %1; cvt.u32.u64 %0, t; }" : "=r"(r) : "l"(p));
    return r;
}
__device__ __forceinline__ float ex2f(float x) { float r; asm("ex2.approx.ftz.f32 %0, %1;" : "=f"(r) : "f"(x)); return r; }
__device__ __forceinline__ float tanh_approx(float x) {
    float r; asm("tanh.approx.f32 %0, %1;" : "=f"(r) : "f"(x)); return r;
}
__device__ __forceinline__ uint32_t pack_h2(float x0, float x1) {
    uint32_t r;
    asm("cvt.rn.f16x2.f32 %0, %1, %2;" : "=r"(r) : "f"(x1), "f"(x0));
    return r;
}
__device__ __forceinline__ void ldsm_x4(uint32_t& r0, uint32_t& r1, uint32_t& r2, uint32_t& r3, uint32_t a) {
    asm volatile("ldmatrix.sync.aligned.m8n8.x4.shared.b16 {%0,%1,%2,%3}, [%4];"
                 : "=r"(r0), "=r"(r1), "=r"(r2), "=r"(r3) : "r"(a));
}
__device__ __forceinline__ void ldsm_x4_t(uint32_t& r0, uint32_t& r1, uint32_t& r2, uint32_t& r3, uint32_t a) {
    asm volatile("ldmatrix.sync.aligned.m8n8.x4.trans.shared.b16 {%0,%1,%2,%3}, [%4];"
                 : "=r"(r0), "=r"(r1), "=r"(r2), "=r"(r3) : "r"(a));
}
__device__ __forceinline__ void mma_f16(float* c, uint32_t a0, uint32_t a1, uint32_t a2, uint32_t a3,
                                        uint32_t b0, uint32_t b1) {
    asm volatile("mma.sync.aligned.m16n8k16.row.col.f32.f16.f16.f32 "
                 "{%0,%1,%2,%3}, {%4,%5,%6,%7}, {%8,%9}, {%0,%1,%2,%3};"
                 : "+f"(c[0]), "+f"(c[1]), "+f"(c[2]), "+f"(c[3])
                 : "r"(a0), "r"(a1), "r"(a2), "r"(a3), "r"(b0), "r"(b1));
}
__device__ __forceinline__ void cp_async16(uint32_t saddr, const void* g) {
    asm volatile("cp.async.cg.shared.global [%0], [%1], 16;" :: "r"(saddr), "l"(g));
}
__device__ __forceinline__ void cp_commit() { asm volatile("cp.async.commit_group;" ::: "memory"); }
__device__ __forceinline__ void cp_wait0()  { asm volatile("cp.async.wait_group 0;" ::: "memory"); }

// ---------------- K2: persistent fused GEMM + tanh + Wf dot + softmax-V + normalize ----------------
// Tile: 64 rows x 128 n; 256 threads (8 warps): warp = (rowblk 0..3, nhalf 0..1)
#define KSTRIDE  272
#define OFF_T    0
#define OFF_WF   512
#define OFF_PART 1024
#define OFF_E    1536
#define OFF_RED  1792
#define OFF_K    2048
#define OFF_WHI  (OFF_K + 64 * KSTRIDE)       // 19456
#define OFF_V    (OFF_WHI + 128 * KSTRIDE)    // 54272 (V stage: 64 rows x 512B)
#define SMEM_TOT (OFF_V + 64 * 512)           // 87040

__global__ void __launch_bounds__(256, 2) k2_gemm(const float* __restrict__ q,
                                                  const float* __restrict__ kk,
                                                  const float* __restrict__ v,
                                                  const float* __restrict__ W1,
                                                  const float* __restrict__ W2,
                                                  const float* __restrict__ wf,
                                                  const float* __restrict__ bf,
                                                  float* __restrict__ out,
                                                  int n4) {
    extern __shared__ char smem[];
    uint32_t sb = smem_u32(smem);
    int tid = threadIdx.x, wid = tid >> 5, lane = tid & 31;

    const int per = NTILE / GRID2;                 // 13
    const int rem = NTILE - per * GRID2;           // 248
    int c = blockIdx.x;
    int start = c * per + (c < rem ? c : rem);
    int cnt   = per + (c < rem ? 1 : 0);

    float bf0 = bf[0];
    if (tid < 128) ((float*)(smem + OFF_WF))[tid] = wf[tid];

    // one-time: W1 fp32 -> fp16 into smem
    {
        const float4* w4 = (const float4*)W1;
        #pragma unroll
        for (int i = 0; i < 16; i++) {
            int gid = i * 256 + tid;               // 0..4095 float4
            int row = gid >> 5, c4 = gid & 31;
            float4 a = w4[gid];
            uint32_t h0 = pack_h2(a.x, a.y);
            uint32_t h1 = pack_h2(a.z, a.w);
            *(uint2*)(smem + OFF_WHI + row * KSTRIDE + c4 * 8) = make_uint2(h0, h1);
        }
    }

    int rb = wid & 3, h = wid >> 2;
    uint32_t a_off = (uint32_t)(rb * 16 + (lane & 15)) * KSTRIDE + (uint32_t)(lane >> 4) * 16;
    uint32_t b_off = (uint32_t)(lane & 15) * KSTRIDE + (uint32_t)h * 128 + (uint32_t)(lane >> 4) * 16;
    const float* t_sm  = (const float*)(smem + OFF_T);
    const float* wf_sm = (const float*)(smem + OFF_WF);
    float* part = (float*)(smem + OFF_PART);
    float* e_sm = (float*)(smem + OFF_E);
    float* red  = (float*)(smem + OFF_RED);
    float* v_sm = (float*)(smem + OFF_V);

    int d_ = tid & 127, g_ = tid >> 7;             // V-accum role
    float va0 = 0.f, va1 = 0.f, va2 = 0.f, va3 = 0.f, dacc = 0.f;

    // prefetch first K tile
    float4 pf[8];
    {
        int g0 = start;
        const float4* kg = (const float4*)(kk + ((size_t)(g0 >> 7) * SK_ + (size_t)(g0 & 127) * 64) * 128);
        #pragma unroll
        for (int i = 0; i < 8; i++) pf[i] = kg[i * 256 + tid];
    }

    int b_cur = -1;
    for (int it = 0; it < cnt; it++) {
        int g = start + it;
        int b = g >> 7, tl = g & 127;

        if (b != b_cur) {
            if (b_cur >= 0) {     // flush previous batch
                atomicAdd(&g_acc[b_cur * 128 + d_], va0 + va1 + va2 + va3);
                va0 = va1 = va2 = va3 = 0.f;
                if (tid == 0) { atomicAdd(&g_denom[b_cur], dacc); dacc = 0.f; }
            }
            if (tid < 128) {      // t[b] = q[b] @ W2
                float a = 0.f;
                const float* qb = q + b * 128;
                #pragma unroll 8
                for (int d = 0; d < 128; d++) a = fmaf(qb[d], W2[d * 128 + tid], a);
                ((float*)(smem + OFF_T))[tid] = a;
            }
            b_cur = b;
        }

        // prefetched fp32 K tile -> fp16 smem
        #pragma unroll
        for (int i = 0; i < 8; i++) {
            int gid = i * 256 + tid;
            int row = gid >> 5, c4 = gid & 31;
            uint32_t h0 = pack_h2(pf[i].x, pf[i].y);
            uint32_t h1 = pack_h2(pf[i].z, pf[i].w);
            *(uint2*)(smem + OFF_K + row * KSTRIDE + c4 * 8) = make_uint2(h0, h1);
        }
        __syncthreads();   // sync1: orders K writes vs MMA, and V-stage writes vs prev V reads

        // stage V tile via cp.async (latency hides under MMA+epilogue)
        {
            const float* vb = v + ((size_t)b * SK_ + (size_t)tl * 64) * 128;
            #pragma unroll
            for (int i = 0; i < 8; i++) {
                int ci = i * 256 + tid;
                int row = ci >> 5, c16 = ci & 31;
                cp_async16(sb + OFF_V + row * 512 + c16 * 16, vb + (size_t)row * 128 + c16 * 4);
            }
            cp_commit();
        }

        // prefetch next K tile
        if (it + 1 < cnt) {
            int gn = g + 1;
            const float4* kg = (const float4*)(kk + ((size_t)(gn >> 7) * SK_ + (size_t)(gn & 127) * 64) * 128);
            #pragma unroll
            for (int i = 0; i < 8; i++) pf[i] = kg[i * 256 + tid];
        }

        // ---- MMA: acc = Khalf @ W1h ----
        float acc[8][4];
        #pragma unroll
        for (int j = 0; j < 8; j++)
            #pragma unroll
            for (int cc = 0; cc < 4; cc++) acc[j][cc] = 0.f;

        uint32_t abase = sb + OFF_K + a_off;
        uint32_t bbase0 = sb + OFF_WHI + b_off;
        #pragma unroll
        for (int kc = 0; kc < 8; kc++) {
            uint32_t a0, a1, a2, a3;
            ldsm_x4(a0, a1, a2, a3, abase + kc * 32);
            uint32_t bbase = bbase0 + kc * (16 * KSTRIDE);
            #pragma unroll
            for (int j4 = 0; j4 < 4; j4++) {
                uint32_t b0, b1, b2, b3;
                ldsm_x4_t(b0, b1, b2, b3, bbase + j4 * 32);
                mma_f16(acc[2 * j4],     a0, a1, a2, a3, b0, b1);
                mma_f16(acc[2 * j4 + 1], a0, a1, a2, a3, b2, b3);
            }
        }

        // ---- epilogue: dot(tanh.approx(acc + t), wf) over this warp's 64 cols ----
        float slow = 0.f, shigh = 0.f;
        #pragma unroll
        for (int j = 0; j < 8; j++) {
            int c0 = h * 64 + j * 8 + 2 * (lane & 3);
            float t0 = t_sm[c0], t1 = t_sm[c0 + 1];
            float w0 = wf_sm[c0], w1 = wf_sm[c0 + 1];
            slow  = fmaf(tanh_approx(acc[j][0] + t0), w0, slow);
            slow  = fmaf(tanh_approx(acc[j][1] + t1), w1, slow);
            shigh = fmaf(tanh_approx(acc[j][2] + t0), w0, shigh);
            shigh = fmaf(tanh_approx(acc[j][3] + t1), w1, shigh);
        }
        #pragma unroll
        for (int s = 1; s <= 2; s <<= 1) {
            slow  += __shfl_xor_sync(0xffffffffu, slow,  s);
            shigh += __shfl_xor_sync(0xffffffffu, shigh, s);
        }
        if ((lane & 3) == 0) {
            int row = rb * 16 + (lane >> 2);
            part[h * 64 + row]     = slow;
            part[h * 64 + row + 8] = shigh;
        }
        __syncthreads();   // sync2

        // logits -> e (unshifted exp); write unnormalized attn_sm; reduce denom
        if (tid < 64) {
            float logit = part[tid] + part[64 + tid] + bf0;
            float e = ex2f(logit * 1.4426950408889634f);
            e_sm[tid] = e;
            out[4096 + (size_t)b * SK_ + (size_t)tl * 64 + tid] = e;
            float s = e;
            #pragma unroll
            for (int sh = 16; sh > 0; sh >>= 1) s += __shfl_xor_sync(0xffffffffu, s, sh);
            if (lane == 0) red[wid] = s;
        }
        cp_wait0();        // V stage complete (per-thread) before the barrier publishes it
        __syncthreads();   // sync3
        if (tid == 0) dacc += red[0] + red[1];

        // V-weighted accumulation from smem: thread (g_, d_) rows [g_*32, g_*32+32)
        {
            const float* vs = v_sm + (size_t)g_ * 32 * 128 + d_;
            const float* ep = e_sm + g_ * 32;
            #pragma unroll
            for (int r = 0; r < 32; r += 4) {
                va0 = fmaf(ep[r],     vs[(r)     * 128], va0);
                va1 = fmaf(ep[r + 1], vs[(r + 1) * 128], va1);
                va2 = fmaf(ep[r + 2], vs[(r + 2) * 128], va2);
                va3 = fmaf(ep[r + 3], vs[(r + 3) * 128], va3);
            }
        }
        // next iteration's sync1 orders smem reuse
    }
    // final flush
    if (b_cur >= 0) {
        atomicAdd(&g_acc[b_cur * 128 + d_], va0 + va1 + va2 + va3);
        if (tid == 0) atomicAdd(&g_denom[b_cur], dacc);
    }

    // ===== grid-wide barrier (all 296 CTAs co-resident: 2/SM guaranteed by smem+launch_bounds) =====
    __syncthreads();                 // all in-CTA work (incl. flush atomics issued) ordered
    if (tid == 0) {
        __threadfence();             // publish atomics + out stores
        atomicAdd(&g_bar, 1u);
        volatile unsigned* vb = &g_bar;
        while (*vb < GRID2) __nanosleep(64);
    }
    __syncthreads();                 // release whole CTA
    __threadfence();                 // acquire: see all CTAs' g_acc/g_denom/out

    // ===== fused normalize (was k4): one float4 per thread; 296*256=75776 >= n4 =====
    {
        float4* out4 = (float4*)out;
        int i = blockIdx.x * 256 + tid;
        if (i < n4) {
            if (i < 1024) {                      // attn region: acc/denom
                int b = i >> 5;
                float4 a = ((float4*)g_acc)[i];
                ((float4*)g_acc)[i] = make_float4(0.f, 0.f, 0.f, 0.f);
                float inv = 1.0f / g_denom[b];
                out4[i] = make_float4(a.x * inv, a.y * inv, a.z * inv, a.w * inv);
            } else {                             // attn_sm region (L2-resident)
                int b = (i - 1024) >> 11;
                float inv = 1.0f / g_denom[b];
                float4 x = out4[i];
                out4[i] = make_float4(x.x * inv, x.y * inv, x.z * inv, x.w * inv);
            }
        }
    }

    // cleanup election: a CTA increments g_tick only after passing the spin,
    // so the last CTA sees g_tick==GRID2-1 => nobody is still reading g_denom/g_bar
    __syncthreads();
    __shared__ int is_last;
    if (tid == 0) {
        __threadfence();
        unsigned t = atomicAdd(&g_tick, 1u);
        is_last = (t == GRID2 - 1);
    }
    __syncthreads();
    if (is_last) {
        if (tid < B_) g_denom[tid] = 0.f;
        if (tid == 0) { g_bar = 0u; __threadfence(); g_tick = 0u; }
    }
}

// ---------------- launch ----------------
extern "C" void kernel_launch(void* const* d_in, const int* in_sizes, int n_in,
                              void* d_out, int out_size) {
    const float* q  = (const float*)d_in[0];
    const float* kk = (const float*)d_in[1];
    const float* v  = (const float*)d_in[2];
    const float* W1 = (const float*)d_in[3];
    const float* W2 = (const float*)d_in[4];
    const float* Wf = (const float*)d_in[5];
    const float* bf = (const float*)d_in[6];
    float* out = (float*)d_out;

    cudaFuncSetAttribute(k2_gemm, cudaFuncAttributeMaxDynamicSharedMemorySize, SMEM_TOT);

    int n4 = out_size / 4;
    k2_gemm<<<GRID2, 256, SMEM_TOT>>>(q, kk, v, W1, W2, Wf, bf, out, n4);
}